// round 3
// baseline (speedup 1.0000x reference)
#include <cuda_runtime.h>

#define Nn 128
#define Dd 512
#define NPAIR 8128            // C(128,2)
#define NTRI  341376          // C(128,3)
#define NROWS (Nn + NPAIR + NTRI)   // 349632
#define EPS   32.0f
#define SHARP 10.0f

__device__ float    g_sq[Nn];
__device__ float    g_d[Nn * Nn];
__device__ float    g_pval[NPAIR];
__device__ unsigned g_pij[NPAIR];
__device__ unsigned g_tri[NTRI];

// --- row squared norms ---------------------------------------------------
__global__ void k_sq(const float* __restrict__ W) {
    int i = threadIdx.x;
    const float4* w = reinterpret_cast<const float4*>(W + (size_t)i * Dd);
    float s = 0.f;
#pragma unroll 8
    for (int k = 0; k < Dd / 4; k++) {
        float4 a = w[k];
        s += a.x * a.x;
        s += a.y * a.y;
        s += a.z * a.z;
        s += a.w * a.w;
    }
    g_sq[i] = s;
}

// --- pairwise distances: d = sqrt(max(sq_i + sq_j - 2*dot, 0)) -----------
__global__ void k_dist(const float* __restrict__ W) {
    int i = blockIdx.x, j = threadIdx.x;
    __shared__ float4 wi[Dd / 4];
    const float4* wg = reinterpret_cast<const float4*>(W + (size_t)i * Dd);
    for (int k = threadIdx.x; k < Dd / 4; k += blockDim.x) wi[k] = wg[k];
    __syncthreads();
    const float4* wj = reinterpret_cast<const float4*>(W + (size_t)j * Dd);
    float dot = 0.f;
#pragma unroll 8
    for (int k = 0; k < Dd / 4; k++) {
        float4 a = wi[k], b = wj[k];
        dot += a.x * b.x;
        dot += a.y * b.y;
        dot += a.z * b.z;
        dot += a.w * b.w;
    }
    float d2 = g_sq[i] + g_sq[j] - 2.f * dot;
    g_d[i * Nn + j] = sqrtf(fmaxf(d2, 0.f));
}

// --- pair table: packed (i,j) + sigmoid value -----------------------------
__global__ void k_pairs() {
    int i = blockIdx.x, j = threadIdx.x;
    if (j <= i) return;
    int p = i * (Nn - 1) - i * (i - 1) / 2 + (j - i - 1);
    float d = g_d[i * Nn + j];
    float val = 1.f / (1.f + __expf(0.f) * 0.f + expf(-SHARP * (EPS - d)));
    g_pval[p] = val;
    g_pij[p]  = (unsigned)i | ((unsigned)j << 8);
}

// --- triple table: packed (i,j,k) + cond bit ------------------------------
__device__ __forceinline__ int C3(int x) { return x * (x - 1) * (x - 2) / 6; }
__device__ __forceinline__ int T2(int x) { return x * (x + 1) / 2; }

__global__ void k_tri() {
    int i = blockIdx.x, j = threadIdx.x;
    if (j <= i || j >= Nn - 1) return;
    int start = C3(Nn) - C3(Nn - i) + T2(Nn - 2 - i) - T2(Nn - j - 1);
    bool aij = g_d[i * Nn + j] <= EPS;
    unsigned base = (unsigned)i | ((unsigned)j << 8);
    for (int k = j + 1; k < Nn; k++) {
        bool c = aij && (g_d[j * Nn + k] <= EPS) && (g_d[i * Nn + k] <= EPS);
        g_tri[start + (k - j - 1)] = base | ((unsigned)k << 16) | (c ? (1u << 24) : 0u);
    }
}

// --- output fill: one thread per float4 (4 columns of one row) ------------
__device__ __forceinline__ void setcol(float4& v, int col, int c0, float val) {
    if (col == c0)          v.x = val;
    else if (col == c0 + 1) v.y = val;
    else if (col == c0 + 2) v.z = val;
    else if (col == c0 + 3) v.w = val;
}

__global__ void __launch_bounds__(256) k_fill(float4* __restrict__ out) {
    int idx = blockIdx.x * 256 + threadIdx.x;   // < NROWS * 32
    int r  = idx >> 5;          // row
    int cg = idx & 31;          // float4 index within row
    int c0 = cg << 2;           // first column of this float4
    float4 v = make_float4(0.f, 0.f, 0.f, 0.f);

    if (r < Nn) {
        setcol(v, r, c0, 1.0f);
    } else if (r < Nn + NPAIR) {
        int p = r - Nn;
        unsigned u = g_pij[p];
        float val = g_pval[p];
        int i = u & 255, j = (u >> 8) & 255;
        setcol(v, i, c0, val);
        setcol(v, j, c0, val);
    } else {
        int t = r - Nn - NPAIR;
        unsigned u = g_tri[t];
        float val = (u >> 24) ? 1.0f : 0.0f;
        int i = u & 255, j = (u >> 8) & 255, k = (u >> 16) & 255;
        setcol(v, i, c0, val);
        setcol(v, j, c0, val);
        setcol(v, k, c0, val);
    }
    out[idx] = v;
}

extern "C" void kernel_launch(void* const* d_in, const int* in_sizes, int n_in,
                              void* d_out, int out_size) {
    const float* W = (const float*)d_in[0];
    float4* out = (float4*)d_out;

    k_sq<<<1, Nn>>>(W);
    k_dist<<<Nn, Nn>>>(W);
    k_pairs<<<Nn, Nn>>>();
    k_tri<<<Nn, Nn>>>();

    int total4 = NROWS * 32;                 // 11,188,224 float4 stores
    k_fill<<<total4 / 256, 256>>>(out);      // 43,704 blocks, exact cover
}

// round 4
// speedup vs baseline: 1.9053x; 1.9053x over previous
#include <cuda_runtime.h>

#define Nn 128
#define Dd 512
#define NPAIR 8128            // C(128,2)
#define NTRI  341376          // C(128,3)
#define NROWS (Nn + NPAIR + NTRI)   // 349632
#define EPS   32.0f
#define SHARP 10.0f

__device__ float    g_d[Nn * Nn];
__device__ float    g_pval[NPAIR];
__device__ unsigned g_pij[NPAIR];
__device__ unsigned g_tri[NTRI];

// --- fused: distances + row norms + pair table ----------------------------
// block i, thread j: dot(W_i, W_j) and sq_j in one pass; sq_i broadcast via smem.
__global__ void k_dist(const float* __restrict__ W) {
    int i = blockIdx.x, j = threadIdx.x;
    __shared__ float4 wi[Dd / 4];
    __shared__ float  s_sqi;
    const float4* wg = reinterpret_cast<const float4*>(W + (size_t)i * Dd);
    for (int k = j; k < Dd / 4; k += Nn) wi[k] = wg[k];
    __syncthreads();

    const float4* wj = reinterpret_cast<const float4*>(W + (size_t)j * Dd);
    float dot = 0.f, sq = 0.f;
#pragma unroll 8
    for (int k = 0; k < Dd / 4; k++) {
        float4 a = wi[k], b = wj[k];
        dot += a.x * b.x; dot += a.y * b.y; dot += a.z * b.z; dot += a.w * b.w;
        sq  += b.x * b.x; sq  += b.y * b.y; sq  += b.z * b.z; sq  += b.w * b.w;
    }
    if (j == i) s_sqi = sq;          // dot(i,i) == sq_i; sq of thread i == sq_i
    __syncthreads();

    float d2 = s_sqi + sq - 2.f * dot;
    float d  = sqrtf(fmaxf(d2, 0.f));
    g_d[i * Nn + j] = d;

    if (j > i) {                      // pair table entry
        int p = i * (2 * Nn - 1 - i) / 2 + (j - i - 1);
        g_pval[p] = 1.f / (1.f + expf(-SHARP * (EPS - d)));
        g_pij[p]  = (unsigned)i | ((unsigned)j << 8);
    }
}

// --- triple table: one block per (i,j) pair, one thread per k --------------
__device__ __forceinline__ int C3(int x) { return x * (x - 1) * (x - 2) / 6; }
__device__ __forceinline__ int T2(int x) { return x * (x + 1) / 2; }
__device__ __forceinline__ int pairoff(int i) { return i * (2 * Nn - 1 - i) / 2; }

__global__ void k_tri(void) {
    int p = blockIdx.x;               // pair index in [0, NPAIR)
    // unrank p -> (i, j): solve i^2 - (2N-1)i + 2p = 0, then integer fixup
    int i = (int)((255.0f - sqrtf(65025.0f - 8.0f * (float)p)) * 0.5f);
    while (pairoff(i + 1) <= p) i++;
    while (pairoff(i) > p) i--;
    int j = i + 1 + (p - pairoff(i));

    int k = j + 1 + threadIdx.x;
    if (k >= Nn) return;

    int start = C3(Nn) - C3(Nn - i) + T2(Nn - 2 - i) - T2(Nn - j - 1);
    bool c = (g_d[i * Nn + j] <= EPS) &&
             (g_d[j * Nn + k] <= EPS) &&
             (g_d[i * Nn + k] <= EPS);
    g_tri[start + (k - j - 1)] =
        (unsigned)i | ((unsigned)j << 8) | ((unsigned)k << 16) | (c ? (1u << 24) : 0u);
}

// --- output fill: one thread per float4 (warp == one row) ------------------
__device__ __forceinline__ void setcol(float4& v, int col, int c0, float val) {
    if (col == c0)          v.x = val;
    else if (col == c0 + 1) v.y = val;
    else if (col == c0 + 2) v.z = val;
    else if (col == c0 + 3) v.w = val;
}

__global__ void __launch_bounds__(256) k_fill(float4* __restrict__ out) {
    int idx = blockIdx.x * 256 + threadIdx.x;   // < NROWS * 32
    int r  = idx >> 5;          // row
    int c0 = (idx & 31) << 2;   // first column of this float4
    float4 v = make_float4(0.f, 0.f, 0.f, 0.f);

    if (r < Nn) {
        setcol(v, r, c0, 1.0f);
    } else if (r < Nn + NPAIR) {
        int p = r - Nn;
        unsigned u = g_pij[p];       // broadcast load within warp
        float val = g_pval[p];
        setcol(v, u & 255, c0, val);
        setcol(v, (u >> 8) & 255, c0, val);
    } else {
        int t = r - Nn - NPAIR;
        unsigned u = g_tri[t];       // broadcast load within warp
        float val = (u >> 24) ? 1.0f : 0.0f;
        setcol(v, u & 255, c0, val);
        setcol(v, (u >> 8) & 255, c0, val);
        setcol(v, (u >> 16) & 255, c0, val);
    }
    __stcs(&out[idx], v);            // streaming store, evict-first
}

extern "C" void kernel_launch(void* const* d_in, const int* in_sizes, int n_in,
                              void* d_out, int out_size) {
    const float* W = (const float*)d_in[0];
    float4* out = (float4*)d_out;

    k_dist<<<Nn, Nn>>>(W);           // distances + norms + pair table (fused)
    k_tri<<<NPAIR, 128>>>();         // triple table, fully parallel

    int total4 = NROWS * 32;         // 11,188,224 float4 stores
    k_fill<<<total4 / 256, 256>>>(out);
}